// round 6
// baseline (speedup 1.0000x reference)
#include <cuda_runtime.h>
#include <math.h>

#define D 128
#define P 17
#define HF 56
#define WF 100
#define BMAX 2
#define VPW 4
#define WARPS_PER_CTA 4
#define FULLMASK 0xffffffffu

// ---------------- device scratch ----------------
__device__ __align__(16) float g_img[BMAX * HF * WF * D];  // NHWC
__device__ __align__(16) float g_kWT[D * D];
__device__ __align__(16) float g_Mi[D * D];   // interleaved: [(a>>1)*D + c]*2 + (a&1)
__device__ __align__(16) float g_W2i[D * D];  // interleaved: [(c>>1)*D + d]*2 + (c&1)
__device__ float g_mb[D];
__device__ float g_u[D];
__device__ float g_vbo[D];
__device__ float g_c0;

__constant__ float2 c_base[P] = {
    {-1.f,-1.f},{-1.f,0.f},{-1.f,1.f},{0.f,-1.f},{0.f,0.f},{0.f,1.f},
    {1.f,-1.f},{1.f,0.f},{1.f,1.f},{-3.f,-3.f},{-3.f,0.f},{-3.f,3.f},
    {0.f,-3.f},{0.f,3.f},{3.f,-3.f},{3.f,0.f},{3.f,3.f}
};

__device__ __forceinline__ float wsum(float v) {
    #pragma unroll
    for (int o = 16; o; o >>= 1) v += __shfl_xor_sync(FULLMASK, v, o);
    return v;
}

// packed dual-fp32 fma: acc = a*b + acc (elementwise on 2 floats)
__device__ __forceinline__ void ffma2(unsigned long long& acc,
                                      unsigned long long a, unsigned long long b) {
    asm("fma.rn.f32x2 %0, %1, %2, %0;" : "+l"(acc) : "l"(a), "l"(b));
}
__device__ __forceinline__ float fsum2(unsigned long long u) {
    float lo, hi;
    asm("mov.b64 {%0,%1}, %2;" : "=f"(lo), "=f"(hi) : "l"(u));
    return lo + hi;
}

// ---------------- prep: tiled NCHW->NHWC transpose ----------------
__global__ void prep_img_t(const float* __restrict__ img) {
    __shared__ float tile[32][33];
    int by = blockIdx.z;             // b*HF + y
    int b = by / HF, y = by % HF;
    int x0 = blockIdx.x * 32, c0 = blockIdx.y * 32;
    int tx = threadIdx.x, ty = threadIdx.y;   // 32 x 8
    #pragma unroll
    for (int i = ty; i < 32; i += 8) {
        int c = c0 + i, x = x0 + tx;
        if (x < WF) tile[i][tx] = img[((size_t)(b * D + c) * HF + y) * WF + x];
    }
    __syncthreads();
    #pragma unroll
    for (int i = ty; i < 32; i += 8) {
        int x = x0 + i, c = c0 + tx;
        if (x < WF) g_img[((size_t)(b * HF + y) * WF + x) * D + c] = tile[tx][i];
    }
}

__global__ void prep_kwt(const float* __restrict__ kW) {
    int t = blockIdx.x * blockDim.x + threadIdx.x;
    if (t >= D * D) return;
    int j = t & (D - 1);
    int e = t >> 7;
    g_kWT[t] = kW[j * D + e];
}

// merged small preps: blocks 0..127 -> M rows, 128..255 -> W2 rows, 256 -> vectors
__global__ void prep_rest(const float* __restrict__ qW, const float* __restrict__ kW,
                          const float* __restrict__ qb, const float* __restrict__ kb,
                          const float* __restrict__ vW, const float* __restrict__ vb,
                          const float* __restrict__ outW) {
    int bid = blockIdx.x;
    int j = threadIdx.x;
    if (bid < D) {                       // M row a = bid
        int a = bid;
        __shared__ float sq[D];
        sq[j] = qW[a * D + j];
        __syncthreads();
        float acc = 0.f;
        #pragma unroll 32
        for (int e = 0; e < D; e++) acc = fmaf(sq[e], g_kWT[e * D + j], acc);
        g_Mi[((a >> 1) * D + j) * 2 + (a & 1)] = acc;
    } else if (bid < 2 * D) {            // W2 row c = bid-128
        int c = bid - D;
        __shared__ float sv[D];
        sv[j] = vW[c * D + j];
        __syncthreads();
        float acc = 0.f;
        #pragma unroll 32
        for (int e = 0; e < D; e++) acc = fmaf(sv[e], outW[e * D + j], acc);
        g_W2i[((c >> 1) * D + j) * 2 + (c & 1)] = acc;
    } else {                             // vectors
        float mb = 0.f, u = 0.f, vo = 0.f;
        #pragma unroll 32
        for (int e = 0; e < D; e++) {
            mb = fmaf(qb[e], kW[j * D + e], mb);
            u  = fmaf(qW[j * D + e], kb[e], u);
            vo = fmaf(vb[e], outW[e * D + j], vo);
        }
        g_mb[j] = mb; g_u[j] = u; g_vbo[j] = vo;
        if (j == 0) {
            float c = 0.f;
            #pragma unroll 32
            for (int e = 0; e < D; e++) c = fmaf(qb[e], kb[e], c);
            g_c0 = c;
        }
    }
}

// ---------------- main fused kernel: 4 voxels per warp ----------------
__global__ void __launch_bounds__(WARPS_PER_CTA * 32)
fusion_main(const float* __restrict__ x_lidar, const int* __restrict__ indices,
            const float* __restrict__ voxel_size, const float* __restrict__ pc_range,
            const float* __restrict__ trans,
            const float* __restrict__ offW, const float* __restrict__ offb,
            const float* __restrict__ outb,
            const int* __restrict__ Himg, const int* __restrict__ Wimg,
            float* __restrict__ out, int N) {
    const int warp = threadIdx.x >> 5;
    const int lane = threadIdx.x & 31;
    const int n0 = (blockIdx.x * WARPS_PER_CTA + warp) * VPW;
    if (n0 >= N) return;

    __shared__ __align__(16) float sx[WARPS_PER_CTA][VPW][D];
    __shared__ __align__(16) float sagg[WARPS_PER_CTA][VPW][D];

    const float du = 2.0f / (float)(WF - 1);
    const float dv = 2.0f / (float)(HF - 1);
    const float scale = 0.1767766953f;               // 32^-0.5

    float cv0 = voxel_size[0] * 8.0f, cv1 = voxel_size[1] * 8.0f, cv2 = voxel_size[2] * 8.0f;
    float pr0 = pc_range[0], pr1 = pc_range[1], pr2 = pc_range[2];
    float wsc = (float)WF / (float)Wimg[0];
    float hsc = (float)HF / (float)Himg[0];

    int   bv[VPW];
    float unv[VPW], vnv[VPW];

    #pragma unroll
    for (int v = 0; v < VPW; v++) {
        int n = n0 + v; if (n >= N) n = N - 1;
        float4 xr = *(const float4*)&x_lidar[(size_t)n * D + 4 * lane];
        *(float4*)&sx[warp][v][4 * lane] = xr;

        int4 vidx = *(const int4*)&indices[(size_t)n * 4];
        bv[v] = vidx.x;
        float ph0 = (float)vidx.w * cv0 + pr0 + cv0 * 0.5f;
        float ph1 = (float)vidx.z * cv1 + pr1 + cv1 * 0.5f;
        float ph2 = (float)vidx.y * cv2 + pr2 + cv2 * 0.5f;
        const float* T = trans + bv[v] * 12;
        float X = T[0]*ph0 + T[1]*ph1 + T[2]*ph2 + T[3];
        float Y = T[4]*ph0 + T[5]*ph1 + T[6]*ph2 + T[7];
        float Z = T[8]*ph0 + T[9]*ph1 + T[10]*ph2 + T[11];
        float depth = fmaxf(Z, 1e-5f);
        unv[v] = 2.0f * ((X / depth * wsc) / (float)(WF - 1)) - 1.0f;
        vnv[v] = 2.0f * ((Y / depth * hsc) / (float)(HF - 1)) - 1.0f;
    }
    __syncwarp();

    // ---- learned offsets (lanes < 17) ----
    float ax[VPW] = {0.f,0.f,0.f,0.f}, ay[VPW] = {0.f,0.f,0.f,0.f};
    if (lane < P) {
        const float2* ow2 = (const float2*)offW;
        #pragma unroll 4
        for (int c = 0; c < D; c++) {
            float2 w = ow2[c * P + lane];
            #pragma unroll
            for (int v = 0; v < VPW; v++) {
                float xc = sx[warp][v][c];
                ax[v] = fmaf(xc, w.x, ax[v]);
                ay[v] = fmaf(xc, w.y, ay[v]);
            }
        }
    }
    float gx[VPW], gy[VPW], ln[VPW];
    unsigned vm[VPW];
    {
        float2 ob = (lane < P) ? ((const float2*)offb)[lane] : make_float2(0.f, 0.f);
        float bx = (lane < P) ? c_base[lane].x : 0.f;
        float by = (lane < P) ? c_base[lane].y : 0.f;
        #pragma unroll
        for (int v = 0; v < VPW; v++) {
            float dx = tanhf(ax[v] + ob.x) * (1.5f * du);
            float dy = tanhf(ay[v] + ob.y) * (1.5f * dv);
            gx[v] = unv[v] + bx * du + dx;
            gy[v] = vnv[v] + by * dv + dy;
            ln[v] = sqrtf(dx * dx + dy * dy);
            bool val = (lane < P) && (fabsf(gx[v]) <= 1.0f) && (fabsf(gy[v]) <= 1.0f);
            vm[v] = __ballot_sync(FULLMASK, val);
        }
    }

    // ---- q . k_b per voxel ----
    float4 u4 = *(const float4*)&g_u[4 * lane];
    float c0 = g_c0;
    float qdk[VPW];
    #pragma unroll
    for (int v = 0; v < VPW; v++) {
        float4 xr = *(const float4*)&sx[warp][v][4 * lane];
        qdk[v] = wsum(xr.x*u4.x + xr.y*u4.y + xr.z*u4.z + xr.w*u4.w) + c0;
    }

    // ---- qk = x @ M + mb via packed f32x2 (interleaved even/odd-a partials) ----
    unsigned long long accM[VPW][4];
    #pragma unroll
    for (int v = 0; v < VPW; v++)
        accM[v][0] = accM[v][1] = accM[v][2] = accM[v][3] = 0ull;
    #pragma unroll 2
    for (int a2 = 0; a2 < D / 2; a2++) {
        const float* wp = &g_Mi[(a2 * D + 4 * lane) * 2];
        ulonglong2 w01 = *(const ulonglong2*)wp;         // pairs for c0, c1
        ulonglong2 w23 = *(const ulonglong2*)(wp + 4);   // pairs for c2, c3
        #pragma unroll
        for (int v = 0; v < VPW; v++) {
            unsigned long long x2 = *(const unsigned long long*)&sx[warp][v][2 * a2];
            ffma2(accM[v][0], x2, w01.x);
            ffma2(accM[v][1], x2, w01.y);
            ffma2(accM[v][2], x2, w23.x);
            ffma2(accM[v][3], x2, w23.y);
        }
    }
    float4 qk[VPW];
    {
        float4 mb4 = *(const float4*)&g_mb[4 * lane];
        #pragma unroll
        for (int v = 0; v < VPW; v++) {
            qk[v].x = fsum2(accM[v][0]) + mb4.x;
            qk[v].y = fsum2(accM[v][1]) + mb4.y;
            qk[v].z = fsum2(accM[v][2]) + mb4.z;
            qk[v].w = fsum2(accM[v][3]) + mb4.w;
        }
    }

    // ---- per-voxel gather + online softmax + stats ----
    float s_n[VPW];
    #pragma unroll
    for (int v = 0; v < VPW; v++) {
        const float* ib = g_img + (size_t)bv[v] * (HF * WF * D);
        float m_run = -3.0e38f, ssum = 0.f;
        float4 agg = make_float4(0.f,0.f,0.f,0.f);
        float myattn = 0.f;

        for (int p = 0; p < P; p++) {
            if (!((vm[v] >> p) & 1u)) continue;
            float gxp = __shfl_sync(FULLMASK, gx[v], p);
            float gyp = __shfl_sync(FULLMASK, gy[v], p);
            float px = (gxp + 1.0f) * 0.5f * (float)(WF - 1);
            float py = (gyp + 1.0f) * 0.5f * (float)(HF - 1);
            float fx0 = floorf(px), fy0 = floorf(py);
            int ix = (int)fx0, iy = (int)fy0;
            float fx = px - fx0, fy = py - fy0;
            float4 feat = make_float4(0.f,0.f,0.f,0.f);
            #pragma unroll
            for (int t = 0; t < 4; t++) {
                int dxt = t & 1, dyt = t >> 1;
                int xc = ix + dxt, yc = iy + dyt;
                if (xc >= 0 && xc < WF && yc >= 0 && yc < HF) {
                    float w = (dxt ? fx : 1.0f - fx) * (dyt ? fy : 1.0f - fy);
                    float4 f = *(const float4*)&ib[(yc * WF + xc) * D + 4 * lane];
                    feat.x = fmaf(w, f.x, feat.x); feat.y = fmaf(w, f.y, feat.y);
                    feat.z = fmaf(w, f.z, feat.z); feat.w = fmaf(w, f.w, feat.w);
                }
            }
            float pd = feat.x*qk[v].x + feat.y*qk[v].y + feat.z*qk[v].z + feat.w*qk[v].w;
            float a = (wsum(pd) + qdk[v]) * scale;
            float nm = fmaxf(m_run, a);
            float cc = expf(m_run - nm);
            float e  = expf(a - nm);
            ssum = ssum * cc + e;
            agg.x = agg.x * cc + e * feat.x; agg.y = agg.y * cc + e * feat.y;
            agg.z = agg.z * cc + e * feat.z; agg.w = agg.w * cc + e * feat.w;
            m_run = nm;
            if (lane == p) myattn = a;
        }

        bool anyv = (vm[v] != 0u);
        float inv_s = anyv ? (1.0f / ssum) : 0.f;
        s_n[v] = anyv ? 1.0f : 0.f;
        float4 an = make_float4(agg.x*inv_s, agg.y*inv_s, agg.z*inv_s, agg.w*inv_s);
        *(float4*)&sagg[warp][v][4 * lane] = an;

        float wn = (lane < P && ((vm[v] >> lane) & 1u)) ? expf(myattn - m_run) * inv_s : 0.f;
        float pe = fmaxf(wn, 1e-6f);
        float ent  = wsum(lane < P ? (-pe * logf(pe)) : 0.f);
        float lsum = wsum(lane < P ? ln[v] : 0.f);
        int n = n0 + v;
        if (lane == 0 && n < N) {
            size_t base = (size_t)N * D;
            out[base + n] = (float)__popc(vm[v]) / 17.0f;
            float oscale = 1.5f * fmaxf(sqrtf(du*du + dv*dv), 1e-6f);
            float instab = (lsum / 17.0f) / oscale;
            out[base + N + n] = fminf(fmaxf(expf(-instab), 0.f), 1.f);
            float focus = 1.0f - ent / logf(17.0f);
            out[base + 2 * (size_t)N + n] = fminf(fmaxf(focus, 0.f), 1.f);
        }
    }
    __syncwarp();

    // ---- out = agg @ W2 via packed f32x2 + s_n*vbo + outb ----
    unsigned long long accO[VPW][4];
    #pragma unroll
    for (int v = 0; v < VPW; v++)
        accO[v][0] = accO[v][1] = accO[v][2] = accO[v][3] = 0ull;
    #pragma unroll 2
    for (int c2 = 0; c2 < D / 2; c2++) {
        const float* wp = &g_W2i[(c2 * D + 4 * lane) * 2];
        ulonglong2 w01 = *(const ulonglong2*)wp;
        ulonglong2 w23 = *(const ulonglong2*)(wp + 4);
        #pragma unroll
        for (int v = 0; v < VPW; v++) {
            unsigned long long a2 = *(const unsigned long long*)&sagg[warp][v][2 * c2];
            ffma2(accO[v][0], a2, w01.x);
            ffma2(accO[v][1], a2, w01.y);
            ffma2(accO[v][2], a2, w23.x);
            ffma2(accO[v][3], a2, w23.y);
        }
    }
    {
        float4 vbo = *(const float4*)&g_vbo[4 * lane];
        float4 ob4 = *(const float4*)&outb[4 * lane];
        #pragma unroll
        for (int v = 0; v < VPW; v++) {
            int n = n0 + v;
            if (n >= N) continue;
            float4 o;
            o.x = fsum2(accO[v][0]) + fmaf(s_n[v], vbo.x, ob4.x);
            o.y = fsum2(accO[v][1]) + fmaf(s_n[v], vbo.y, ob4.y);
            o.z = fsum2(accO[v][2]) + fmaf(s_n[v], vbo.z, ob4.z);
            o.w = fsum2(accO[v][3]) + fmaf(s_n[v], vbo.w, ob4.w);
            *(float4*)&out[(size_t)n * D + 4 * lane] = o;
        }
    }
}

// ---------------- launch ----------------
extern "C" void kernel_launch(void* const* d_in, const int* in_sizes, int n_in,
                              void* d_out, int out_size) {
    const float* x_lidar = (const float*)d_in[0];
    const int*   indices = (const int*)d_in[1];
    const float* img     = (const float*)d_in[2];
    const float* vsize   = (const float*)d_in[3];
    const float* pcr     = (const float*)d_in[4];
    const float* trans   = (const float*)d_in[5];
    const float* offW    = (const float*)d_in[6];
    const float* offb    = (const float*)d_in[7];
    const float* qW      = (const float*)d_in[8];
    const float* qb      = (const float*)d_in[9];
    const float* kW      = (const float*)d_in[10];
    const float* kb      = (const float*)d_in[11];
    const float* vW      = (const float*)d_in[12];
    const float* vb      = (const float*)d_in[13];
    const float* outW    = (const float*)d_in[14];
    const float* outb    = (const float*)d_in[15];
    const int*   Himg    = (const int*)d_in[16];
    const int*   Wimg    = (const int*)d_in[17];

    int N = in_sizes[0] / D;
    int B = in_sizes[5] / 12;
    if (B > BMAX) B = BMAX;

    dim3 tgrid((WF + 31) / 32, D / 32, B * HF);
    prep_img_t<<<tgrid, dim3(32, 8)>>>(img);
    prep_kwt<<<(D * D + 255) / 256, 256>>>(kW);
    prep_rest<<<2 * D + 1, D>>>(qW, kW, qb, kb, vW, vb, outW);

    int voxPerCta = WARPS_PER_CTA * VPW;
    int blocks = (N + voxPerCta - 1) / voxPerCta;
    fusion_main<<<blocks, WARPS_PER_CTA * 32>>>(
        x_lidar, indices, vsize, pcr, trans, offW, offb, outb,
        Himg, Wimg, (float*)d_out, N);
}